// round 15
// baseline (speedup 1.0000x reference)
#include <cuda_runtime.h>

#define HH 768
#define WW 768
#define CC 64
#define NSEG 385
#define NTHREADS 64
#define PER_T (HH / NTHREADS)     // 12 mask elems per scan thread
#define GRID_A 4736               // 148 SM x 32 CTA slots

// ---- scratch (device globals; no allocations allowed) ----
__device__ float4 g_cellmean[(size_t)NSEG * NSEG * 16];   // compact, ~9.4MB used
__device__ int    g_row_id_d[HH];
__device__ int    g_col_id_d[WW];
__device__ int    g_row_cell[HH];    // row_id[y] * ncol (precomputed cell base)
__device__ int    g_ctr = 0;         // work-stealing ticket; reset by bcast_kernel

// ---------------------------------------------------------------------------
// Kernel A: per-cell means, WORK-STEALING warp-per-cell.
//   prolog: every block redundantly scans both masks -> SMEM segment tables;
//           block 0 publishes per-pixel ids + row cell bases for kernel B.
//   main:   warps pull 2-cell batches from a global atomic ticket; the NEXT
//           ticket is fetched before processing the current batch, hiding the
//           ATOMG latency. Inner loop is the R8-measured-optimal form:
//           lanes = 16 channel-quads x 2 x-parities, 512B contiguous access,
//           ONE shfl_xor(16) reduce, 256B store to compact cellmean.
// ---------------------------------------------------------------------------
__global__ void __launch_bounds__(NTHREADS, 32)
sum_kernel(const float* __restrict__ in,
           const int* __restrict__ h_mask,
           const int* __restrict__ v_mask) {
    __shared__ int s_row_start[NSEG + 1];
    __shared__ int s_col_start[NSEG + 1];
    __shared__ int s_tmp[2];
    __shared__ int s_nrow, s_ncol;

    const int t = threadIdx.x;
    const int lane = t & 31, w = t >> 5;
    const bool pub = (blockIdx.x == 0);

    // ---- prolog: build segment starts for both masks ----
    #pragma unroll
    for (int axis = 0; axis < 2; ++axis) {
        const int* m = (axis == 0) ? h_mask : v_mask;
        int* start   = (axis == 0) ? s_row_start : s_col_start;
        int* gid     = (axis == 0) ? g_row_id_d : g_col_id_d;

        const int base = t * PER_T;
        int pm = (base == 0) ? 1 : m[base - 1];   // pm=1 at i=0 forces rise[0]=0
        int rises = 0, cnt = 0;
        #pragma unroll
        for (int k = 0; k < PER_T; ++k) {
            const int mv = m[base + k];
            const int r = (mv == 1 && pm == 0);
            rises |= (r << k);
            cnt += r;
            pm = mv;
        }
        int v = cnt;
        #pragma unroll
        for (int o = 1; o < 32; o <<= 1) {
            int n = __shfl_up_sync(0xFFFFFFFFu, v, o);
            if (lane >= o) v += n;
        }
        if (lane == 31) s_tmp[w] = v;
        __syncthreads();
        const int add   = (w == 1) ? s_tmp[0] : 0;
        const int total = s_tmp[0] + s_tmp[1];
        const int excl  = v + add - cnt;

        int sid = excl;
        #pragma unroll
        for (int k = 0; k < PER_T; ++k) {
            if ((rises >> k) & 1) { ++sid; start[sid] = base + k; }
            if (pub) gid[base + k] = sid;
        }
        const int nseg = total + 1;
        if (t == 0) {
            start[0] = 0; start[nseg] = HH;
            if (axis == 0) s_nrow = nseg; else s_ncol = nseg;
        }
        __syncthreads();
    }

    const int nrow = s_nrow, ncol = s_ncol;
    const int total_cells = nrow * ncol;

    // block 0: publish precomputed row cell bases (row_id * ncol)
    if (pub) {
        #pragma unroll
        for (int k = 0; k < PER_T; ++k) {
            const int yy = t * PER_T + k;
            g_row_cell[yy] = g_row_id_d[yy] * ncol;
        }
    }

    const int cg = lane & 15;     // channel quad
    const int xo = lane >> 4;     // x parity

    // ---- main: work-stealing, 2 cells per ticket, prefetched ----
    int cur = 0;
    if (lane == 0) cur = atomicAdd(&g_ctr, 2);
    cur = __shfl_sync(0xFFFFFFFFu, cur, 0);

    while (cur < total_cells) {
        int nxt = 0;
        if (lane == 0) nxt = atomicAdd(&g_ctr, 2);   // in flight during work
        nxt = __shfl_sync(0xFFFFFFFFu, nxt, 0);

        #pragma unroll
        for (int k = 0; k < 2; ++k) {
            const int cell = cur + k;
            if (cell >= total_cells) break;

            const int rseg = cell / ncol;
            const int cseg = cell - rseg * ncol;
            const int cs = s_col_start[cseg], ce = s_col_start[cseg + 1];
            const int rs = s_row_start[rseg], re = s_row_start[rseg + 1];

            float4 a0 = make_float4(0.f, 0.f, 0.f, 0.f);
            float4 a1 = make_float4(0.f, 0.f, 0.f, 0.f);

            int y = rs;
            for (; y + 1 < re; y += 2) {
                const float4* r0 = reinterpret_cast<const float4*>(
                    in + (size_t)y * WW * CC);
                const float4* r1 = r0 + WW * (CC / 4);
                #pragma unroll 2
                for (int x = cs + xo; x < ce; x += 2) {
                    const float4 v0 = __ldcs(&r0[x * 16 + cg]);
                    const float4 v1 = __ldcs(&r1[x * 16 + cg]);
                    a0.x += v0.x; a0.y += v0.y; a0.z += v0.z; a0.w += v0.w;
                    a1.x += v1.x; a1.y += v1.y; a1.z += v1.z; a1.w += v1.w;
                }
            }
            if (y < re) {
                const float4* r0 = reinterpret_cast<const float4*>(
                    in + (size_t)y * WW * CC);
                #pragma unroll 2
                for (int x = cs + xo; x < ce; x += 2) {
                    const float4 v0 = __ldcs(&r0[x * 16 + cg]);
                    a0.x += v0.x; a0.y += v0.y; a0.z += v0.z; a0.w += v0.w;
                }
            }
            a0.x += a1.x; a0.y += a1.y; a0.z += a1.z; a0.w += a1.w;

            // single-stage reduce across the two x parities (lanes +-16)
            a0.x += __shfl_xor_sync(0xFFFFFFFFu, a0.x, 16);
            a0.y += __shfl_xor_sync(0xFFFFFFFFu, a0.y, 16);
            a0.z += __shfl_xor_sync(0xFFFFFFFFu, a0.z, 16);
            a0.w += __shfl_xor_sync(0xFFFFFFFFu, a0.w, 16);

            if (xo == 0) {
                const float inv = 1.0f / (float)((re - rs) * (ce - cs));
                g_cellmean[(size_t)cell * 16 + cg] =
                    make_float4(a0.x * inv, a0.y * inv, a0.z * inv, a0.w * inv);
            }
        }
        cur = nxt;
    }
}

// ---------------------------------------------------------------------------
// Kernel B: broadcast (R13-validated: 26.7us).
//   grid = (12, 768): blockIdx.y = pixel row, ILP=4 independent gather->store
//   chains per thread, contiguous 4KB coalesced sweeps, __stcs stores.
//   Also resets the work-stealing ticket for the next graph replay
//   (stream-ordered: runs strictly after sum_kernel completes).
// ---------------------------------------------------------------------------
#define B_ILP 4
#define ROW_F4 (WW * (CC / 4))                 // 12288 float4 per pixel row
#define B_BLOCKS_X (ROW_F4 / (256 * B_ILP))    // 12

__global__ void __launch_bounds__(256)
bcast_kernel(float4* __restrict__ out) {
    if (blockIdx.x == 0 && blockIdx.y == 0 && threadIdx.x == 0)
        g_ctr = 0;                              // reset ticket for next launch

    const int y = blockIdx.y;
    const int rowbase_cell = __ldg(&g_row_cell[y]);
    float4* rowp = out + (size_t)y * ROW_F4;

    const int tid0 = blockIdx.x * 256 + threadIdx.x;

    #pragma unroll
    for (int k = 0; k < B_ILP; ++k) {
        const int i = tid0 + k * (B_BLOCKS_X * 256);   // stride 3072
        const int x = i >> 4;
        const int q = i & 15;
        const int cell = rowbase_cell + __ldg(&g_col_id_d[x]);
        const float4 v = __ldg(&g_cellmean[(size_t)cell * 16 + q]);
        __stcs(&rowp[i], v);
    }
}

// ---------------------------------------------------------------------------
extern "C" void kernel_launch(void* const* d_in, const int* in_sizes, int n_in,
                              void* d_out, int out_size) {
    const float* in = (const float*)d_in[0];
    const int*   hm = (const int*)d_in[1];
    const int*   vm = (const int*)d_in[2];
    float*       out = (float*)d_out;

    sum_kernel<<<GRID_A, NTHREADS>>>(in, hm, vm);
    bcast_kernel<<<dim3(B_BLOCKS_X, HH), 256>>>(reinterpret_cast<float4*>(out));
}

// round 17
// speedup vs baseline: 1.1698x; 1.1698x over previous
#include <cuda_runtime.h>

#define HH 768
#define WW 768
#define CC 64
#define NSEG 385
#define NTHREADS 64
#define PER_T (HH / NTHREADS)     // 12 mask elems per scan thread
#define GRID_A 4736               // 148 SM x 32 CTA slots
#define NWARPS_A (GRID_A * 2)
#define TOTALPX (HH * WW)         // 589824

// ---- scratch (device globals; no allocations allowed) ----
__device__ float4 g_cellmean[(size_t)NSEG * NSEG * 16];   // compact, ~9.4MB used
__device__ int    g_row_id_d[HH];
__device__ int    g_col_id_d[WW];
__device__ int    g_row_cell[HH];    // row_id[y] * ncol (precomputed cell base)

// ---------------------------------------------------------------------------
// Kernel A: per-cell means, DETERMINISTIC AREA-BALANCED warp assignment.
//   prolog: every block redundantly scans both masks -> SMEM segment tables;
//           block 0 publishes per-pixel ids + row cell bases for kernel B.
//   assignment: cells ordered row-major have starting-pixel offsets
//           cum(r,c) = row_start[r]*768 + rh(r)*col_start[c] (monotone).
//           Warp k owns cells with cum in [k*P/NW, (k+1)*P/NW): equal-area
//           contiguous runs found by two binary searches on the SMEM tables.
//           No atomics, no communication, near-zero tail.
//   inner loop: R8-measured-optimal (16 quads x 2 x-parities, 512B access,
//           ONE shfl_xor(16), 256B store to compact cellmean).
// ---------------------------------------------------------------------------
__global__ void __launch_bounds__(NTHREADS, 28)
sum_kernel(const float* __restrict__ in,
           const int* __restrict__ h_mask,
           const int* __restrict__ v_mask) {
    __shared__ int s_row_start[NSEG + 1];
    __shared__ int s_col_start[NSEG + 1];
    __shared__ int s_tmp[2];
    __shared__ int s_nrow, s_ncol;

    const int t = threadIdx.x;
    const int lane = t & 31, w = t >> 5;
    const bool pub = (blockIdx.x == 0);

    // ---- prolog: build segment starts for both masks ----
    #pragma unroll
    for (int axis = 0; axis < 2; ++axis) {
        const int* m = (axis == 0) ? h_mask : v_mask;
        int* start   = (axis == 0) ? s_row_start : s_col_start;
        int* gid     = (axis == 0) ? g_row_id_d : g_col_id_d;

        const int base = t * PER_T;
        int pm = (base == 0) ? 1 : m[base - 1];   // pm=1 at i=0 forces rise[0]=0
        int rises = 0, cnt = 0;
        #pragma unroll
        for (int k = 0; k < PER_T; ++k) {
            const int mv = m[base + k];
            const int r = (mv == 1 && pm == 0);
            rises |= (r << k);
            cnt += r;
            pm = mv;
        }
        int v = cnt;
        #pragma unroll
        for (int o = 1; o < 32; o <<= 1) {
            int n = __shfl_up_sync(0xFFFFFFFFu, v, o);
            if (lane >= o) v += n;
        }
        if (lane == 31) s_tmp[w] = v;
        __syncthreads();
        const int add   = (w == 1) ? s_tmp[0] : 0;
        const int total = s_tmp[0] + s_tmp[1];
        const int excl  = v + add - cnt;

        int sid = excl;
        #pragma unroll
        for (int k = 0; k < PER_T; ++k) {
            if ((rises >> k) & 1) { ++sid; start[sid] = base + k; }
            if (pub) gid[base + k] = sid;
        }
        const int nseg = total + 1;
        if (t == 0) {
            start[0] = 0; start[nseg] = HH;
            if (axis == 0) s_nrow = nseg; else s_ncol = nseg;
        }
        __syncthreads();
    }

    const int nrow = s_nrow, ncol = s_ncol;

    // block 0: publish precomputed row cell bases (row_id * ncol)
    if (pub) {
        #pragma unroll
        for (int k = 0; k < PER_T; ++k) {
            const int yy = t * PER_T + k;
            g_row_cell[yy] = g_row_id_d[yy] * ncol;
        }
    }

    const int cg = lane & 15;     // channel quad
    const int xo = lane >> 4;     // x parity
    const int gw = blockIdx.x * 2 + w;

    // ---- area-balanced range for this warp: cum in [T0, T1) ----
    const long long T0 = (long long)((unsigned long long)gw * TOTALPX / NWARPS_A);
    const long long T1 = (long long)((unsigned long long)(gw + 1) * TOTALPX / NWARPS_A);

    // largest r with row_start[r]*768 <= T0
    int lo = 0, hi = nrow - 1;
    while (lo < hi) {
        const int mid = (lo + hi + 1) >> 1;
        if ((long long)s_row_start[mid] * WW <= T0) lo = mid; else hi = mid - 1;
    }
    int r = lo;
    {
        const long long rem = T0 - (long long)s_row_start[r] * WW;
        const long long rh  = s_row_start[r + 1] - s_row_start[r];
        // smallest c with rh*col_start[c] >= rem
        lo = 0; hi = ncol;
        while (lo < hi) {
            const int mid = (lo + hi) >> 1;
            if (rh * s_col_start[mid] >= rem) hi = mid; else lo = mid + 1;
        }
        if (lo == ncol) { ++r; lo = 0; }
    }
    int c = lo;

    // ---- process contiguous run of cells with cum in [T0, T1) ----
    while (r < nrow) {
        const int rs = s_row_start[r], re = s_row_start[r + 1];
        const int cs = s_col_start[c], ce = s_col_start[c + 1];
        const long long cum = (long long)rs * WW + (long long)(re - rs) * cs;
        if (cum >= T1) break;

        float4 a0 = make_float4(0.f, 0.f, 0.f, 0.f);
        float4 a1 = make_float4(0.f, 0.f, 0.f, 0.f);

        int y = rs;
        for (; y + 1 < re; y += 2) {
            const float4* r0 = reinterpret_cast<const float4*>(
                in + (size_t)y * WW * CC);
            const float4* r1 = r0 + WW * (CC / 4);
            #pragma unroll 2
            for (int x = cs + xo; x < ce; x += 2) {
                const float4 v0 = __ldcs(&r0[x * 16 + cg]);
                const float4 v1 = __ldcs(&r1[x * 16 + cg]);
                a0.x += v0.x; a0.y += v0.y; a0.z += v0.z; a0.w += v0.w;
                a1.x += v1.x; a1.y += v1.y; a1.z += v1.z; a1.w += v1.w;
            }
        }
        if (y < re) {
            const float4* r0 = reinterpret_cast<const float4*>(
                in + (size_t)y * WW * CC);
            #pragma unroll 2
            for (int x = cs + xo; x < ce; x += 2) {
                const float4 v0 = __ldcs(&r0[x * 16 + cg]);
                a0.x += v0.x; a0.y += v0.y; a0.z += v0.z; a0.w += v0.w;
            }
        }
        a0.x += a1.x; a0.y += a1.y; a0.z += a1.z; a0.w += a1.w;

        // single-stage reduce across the two x parities (lanes +-16)
        a0.x += __shfl_xor_sync(0xFFFFFFFFu, a0.x, 16);
        a0.y += __shfl_xor_sync(0xFFFFFFFFu, a0.y, 16);
        a0.z += __shfl_xor_sync(0xFFFFFFFFu, a0.z, 16);
        a0.w += __shfl_xor_sync(0xFFFFFFFFu, a0.w, 16);

        if (xo == 0) {
            const float inv = 1.0f / (float)((re - rs) * (ce - cs));
            g_cellmean[((size_t)r * ncol + c) * 16 + cg] =
                make_float4(a0.x * inv, a0.y * inv, a0.z * inv, a0.w * inv);
        }

        if (++c == ncol) { c = 0; ++r; }
    }
}

// ---------------------------------------------------------------------------
// Kernel B: broadcast (R13-validated: 26.7us).
//   grid = (12, 768): blockIdx.y = pixel row, ILP=4 independent gather->store
//   chains per thread, contiguous 4KB coalesced sweeps, __stcs stores.
// ---------------------------------------------------------------------------
#define B_ILP 4
#define ROW_F4 (WW * (CC / 4))                 // 12288 float4 per pixel row
#define B_BLOCKS_X (ROW_F4 / (256 * B_ILP))    // 12

__global__ void __launch_bounds__(256)
bcast_kernel(float4* __restrict__ out) {
    const int y = blockIdx.y;
    const int rowbase_cell = __ldg(&g_row_cell[y]);
    float4* rowp = out + (size_t)y * ROW_F4;

    const int tid0 = blockIdx.x * 256 + threadIdx.x;

    #pragma unroll
    for (int k = 0; k < B_ILP; ++k) {
        const int i = tid0 + k * (B_BLOCKS_X * 256);   // stride 3072
        const int x = i >> 4;
        const int q = i & 15;
        const int cell = rowbase_cell + __ldg(&g_col_id_d[x]);
        const float4 v = __ldg(&g_cellmean[(size_t)cell * 16 + q]);
        __stcs(&rowp[i], v);
    }
}

// ---------------------------------------------------------------------------
extern "C" void kernel_launch(void* const* d_in, const int* in_sizes, int n_in,
                              void* d_out, int out_size) {
    const float* in = (const float*)d_in[0];
    const int*   hm = (const int*)d_in[1];
    const int*   vm = (const int*)d_in[2];
    float*       out = (float*)d_out;

    sum_kernel<<<GRID_A, NTHREADS>>>(in, hm, vm);
    bcast_kernel<<<dim3(B_BLOCKS_X, HH), 256>>>(reinterpret_cast<float4*>(out));
}